// round 9
// baseline (speedup 1.0000x reference)
#include <cuda_runtime.h>
#include <cstdint>

typedef unsigned long long u64;

#define BATCH 2
#define HH 96
#define WW 96
#define CC 128
#define KD 64
#define NPIX (BATCH * HH * WW)   // 18432

__device__ float g_q[NPIX * KD];
__device__ float g_k[NPIX * KD];

// ---- packed f32x2 helpers ----
__device__ __forceinline__ u64 pack2(float lo, float hi) {
    u64 r; asm("mov.b64 %0, {%1, %2};" : "=l"(r) : "f"(lo), "f"(hi)); return r;
}
__device__ __forceinline__ u64 dup2(float v) { return pack2(v, v); }
__device__ __forceinline__ void fma2(u64& d, u64 a, u64 b) {
    asm("fma.rn.f32x2 %0, %1, %2, %0;" : "+l"(d) : "l"(a), "l"(b));
}
__device__ __forceinline__ float hsum2(u64 v) {
    float lo, hi; asm("mov.b64 {%0, %1}, %2;" : "=f"(lo), "=f"(hi) : "l"(v));
    return lo + hi;
}
__device__ __forceinline__ void lds2(u64& a, u64& b, const void* p) {  // 16B aligned
    unsigned ad = (unsigned)__cvta_generic_to_shared(p);
    asm("ld.shared.v2.b64 {%0, %1}, [%2];" : "=l"(a), "=l"(b) : "r"(ad));
}
__device__ __forceinline__ u64 lds1(const void* p) {                   // 8B aligned
    unsigned ad = (unsigned)__cvta_generic_to_shared(p);
    u64 r; asm("ld.shared.b64 %0, [%1];" : "=l"(r) : "r"(ad)); return r;
}
__device__ __forceinline__ void sts2(void* p, u64 a, u64 b) {
    unsigned ad = (unsigned)__cvta_generic_to_shared(p);
    asm volatile("st.shared.v2.b64 [%0], {%1, %2};" :: "r"(ad), "l"(a), "l"(b));
}
__device__ __forceinline__ void cpasync16(float* dst, const float* src, int sz) {
    unsigned daddr = (unsigned)__cvta_generic_to_shared(dst);
    asm volatile("cp.async.cg.shared.global [%0], [%1], 16, %2;"
                 :: "r"(daddr), "l"(src), "r"(sz));
}

// ---------------------------------------------------------------------------
// q/k projection: C[M,64] = A[M,128] @ W[128,64] + bias.
// 512 threads, BM=128, thread tile 4 rows (ty+32i) x 4 cols. Twin u64
// pair-tables (16B lane stride, conflict-free). 2 CTAs/SM -> 32 warps/SM.
// ---------------------------------------------------------------------------
#define ASP 132

__global__ __launch_bounds__(512, 2) void gemm_qk_kernel(
    const float* __restrict__ Q,  const float* __restrict__ K,
    const float* __restrict__ Wq, const float* __restrict__ Wk,
    const float* __restrict__ bq, const float* __restrict__ bk,
    float* __restrict__ qout,     float* __restrict__ kout)
{
    extern __shared__ float smf[];
    float* As   = smf;                         // [128][132]
    u64*   tabA = (u64*)(smf + 128 * ASP);     // [64 kb][32]
    u64*   tabB = tabA + 64 * 32;              // [64 kb][32]

    const bool isK = (blockIdx.y != 0);
    const float* A    = isK ? K    : Q;
    const float* W    = isK ? Wk   : Wq;
    const float* bias = isK ? bk   : bq;
    float*       C    = isK ? kout : qout;

    const int m0 = blockIdx.x * 128;
    const int t  = threadIdx.x;

    // Stage A tile (coalesced float4, rows 528B = conflict-free)
    for (int i = t; i < 4096; i += 512) {
        int r = i >> 5, c4 = i & 31;
        float4 v = *reinterpret_cast<const float4*>(A + (size_t)(m0 + r) * 128 + c4 * 4);
        *reinterpret_cast<float4*>(As + r * ASP + c4 * 4) = v;
    }
    // Stage W twin pair-tables: item (kb 0..63, g 0..15)
    for (int i = t; i < 1024; i += 512) {
        int kb = i >> 4, g = i & 15;
        float4 r0 = *reinterpret_cast<const float4*>(W + (size_t)(2 * kb)     * 64 + 4 * g);
        float4 r1 = *reinterpret_cast<const float4*>(W + (size_t)(2 * kb + 1) * 64 + 4 * g);
        sts2(tabA + kb * 32 + 2 * g, pack2(r0.x, r1.x), pack2(r0.y, r1.y));
        sts2(tabB + kb * 32 + 2 * g, pack2(r0.z, r1.z), pack2(r0.w, r1.w));
    }
    __syncthreads();

    const int ty = t >> 4, tx = t & 15;   // ty 0..31
    const int col0 = tx * 4;

    u64 acc[4][4];
#pragma unroll
    for (int i = 0; i < 4; i++)
#pragma unroll
        for (int j = 0; j < 4; j++) acc[i][j] = 0ull;

#pragma unroll 4
    for (int kb = 0; kb < 64; kb++) {
        u64 a2[4];
#pragma unroll
        for (int i = 0; i < 4; i++)
            a2[i] = lds1(As + (ty + 32 * i) * ASP + kb * 2);   // 2 addrs/warp, bank-distinct
        u64 w0, w1, w2, w3;
        lds2(w0, w1, tabA + kb * 32 + 2 * tx);                 // 16B lane stride
        lds2(w2, w3, tabB + kb * 32 + 2 * tx);
#pragma unroll
        for (int i = 0; i < 4; i++) {
            fma2(acc[i][0], a2[i], w0);
            fma2(acc[i][1], a2[i], w1);
            fma2(acc[i][2], a2[i], w2);
            fma2(acc[i][3], a2[i], w3);
        }
    }

    float b0 = bias[col0], b1 = bias[col0 + 1], b2 = bias[col0 + 2], b3 = bias[col0 + 3];
#pragma unroll
    for (int i = 0; i < 4; i++) {
        int row = m0 + ty + 32 * i;
        float4 o;
        o.x = hsum2(acc[i][0]) + b0;
        o.y = hsum2(acc[i][1]) + b1;
        o.z = hsum2(acc[i][2]) + b2;
        o.w = hsum2(acc[i][3]) + b3;
        *reinterpret_cast<float4*>(C + (size_t)row * 64 + col0) = o;
    }
}

// ---------------------------------------------------------------------------
// Fused attention + output projection. 8x8 pixel tile, 1024 threads, 288 CTAs.
// smem (floats): sk[196][68] | sw[64][52] | sv[196][132]   (170,112 B)
// Overlays (after phase 4): twin Wv pair-tables (64KB) over sk+sw;
//                           at[64][132] over sv.
// ---------------------------------------------------------------------------
#define TS 8
#define WIN 14
#define SKS 68
#define SVS 132
#define SWS 52
#define ATS 132
#define OFF_SK 0
#define OFF_SW (196 * SKS)              // 13328
#define OFF_SV (OFF_SW + 64 * SWS)      // 16656
#define SM_FLOATS (OFF_SV + 196 * SVS)  // 42528 floats = 170,112 B

__global__ __launch_bounds__(1024, 1) void attn_fused_kernel(
    const float* __restrict__ qbuf,
    const float* __restrict__ kbuf,
    const float* __restrict__ V,
    const float* __restrict__ Wv,
    const float* __restrict__ bv,
    float* __restrict__ out)
{
    extern __shared__ float sm[];
    float* sk   = sm + OFF_SK;      // [196][68]
    float* sw   = sm + OFF_SW;      // [64][52]
    float* sv   = sm + OFF_SV;      // [196][132]
    u64*   tabA = (u64*)sm;         // overlay: [64 kb][64]  (32KB)
    u64*   tabB = tabA + 64 * 64;   // overlay: [64 kb][64]
    float* at   = sv;               // overlay: [64][132]

    const int b   = blockIdx.z;
    const int ty0 = blockIdx.y * TS;
    const int tx0 = blockIdx.x * TS;
    const int t   = threadIdx.x;

    const int p   = t >> 4;                 // pixel 0..63
    const int sub = t & 15;                 // 0..15
    const int pry = p >> 3, prx = p & 7;

    // ---- Phase 1: cp.async V halo -> sv; LDG k halo -> sk ----
    for (int i = t; i < 196 * 32; i += 1024) {
        int r = i >> 5, c4 = i & 31;
        int gy = ty0 - 3 + r / WIN;
        int gx = tx0 - 3 + r % WIN;
        bool ok = (gy >= 0 && gy < HH && gx >= 0 && gx < WW);
        const float* src = V + ((size_t)(b * HH + (ok ? gy : 0)) * WW + (ok ? gx : 0)) * CC + c4 * 4;
        cpasync16(sv + r * SVS + c4 * 4, src, ok ? 16 : 0);
    }
    asm volatile("cp.async.commit_group;");

    for (int i = t; i < 196 * 16; i += 1024) {
        int r = i >> 4, c4 = i & 15;
        int gy = ty0 - 3 + r / WIN;
        int gx = tx0 - 3 + r % WIN;
        float4 v = make_float4(0.f, 0.f, 0.f, 0.f);
        if (gy >= 0 && gy < HH && gx >= 0 && gx < WW)
            v = *reinterpret_cast<const float4*>(
                kbuf + ((size_t)(b * HH + gy) * WW + gx) * KD + c4 * 4);
        *reinterpret_cast<float4*>(sk + r * SKS + c4 * 4) = v;
    }
    __syncthreads();

    // ---- Phase 2: scores. thread = (p, ng=sub&3, chh=sub>>2); uniform 13 iters ----
    // chh (lane bits 2-3) owns 16B-interleaved channel chunks c4 = chh + 4j.
    {
        const int ng  = sub & 3;
        const int chh = sub >> 2;

        u64 q2[8];
        {
            const float* qp_ = qbuf + ((size_t)(b * HH + ty0 + pry) * WW + tx0 + prx) * KD;
#pragma unroll
            for (int j = 0; j < 4; j++) {
                ulonglong2 v = *reinterpret_cast<const ulonglong2*>(qp_ + chh * 4 + j * 16);
                q2[2 * j] = v.x; q2[2 * j + 1] = v.y;
            }
        }

#pragma unroll 2
        for (int ni = 0; ni < 13; ni++) {
            const int n  = ng + ni * 4;
            const int nc = (n < 49) ? n : 48;          // clamp: safe compute
            const int dy = nc / 7, dx = nc - dy * 7;
            const float* kr = sk + ((pry + dy) * WIN + prx + dx) * SKS + chh * 4;
            u64 a0 = 0ull, a1 = 0ull;
#pragma unroll
            for (int j = 0; j < 4; j++) {
                u64 ka, kb2;
                lds2(ka, kb2, kr + j * 16);            // 16B lane stride across chh
                fma2(a0, q2[2 * j], ka);
                fma2(a1, q2[2 * j + 1], kb2);
            }
            float part = hsum2(a0) + hsum2(a1);
            part += __shfl_xor_sync(0xffffffffu, part, 4);   // combine chh (bit 2)
            part += __shfl_xor_sync(0xffffffffu, part, 8);   // combine chh (bit 3)
            if (chh == 0 && n < 49) {
                int gy = ty0 + pry + dy - 3, gx = tx0 + prx + dx - 3;
                bool valid = (gy >= 0 && gy < HH && gx >= 0 && gx < WW);
                sw[p * SWS + n] = valid ? part * 0.125f : -1e30f;
            }
        }
    }
    __syncthreads();

    // ---- Phase 3: issue Wv LDGs into regs; softmax in sw ----
    float4 wr0[2], wr1[2];
#pragma unroll
    for (int r = 0; r < 2; r++) {
        int i = t + 1024 * r;                // (kb 0..63) x (g 0..31)
        int kb = i >> 5, g = i & 31;
        wr0[r] = *reinterpret_cast<const float4*>(Wv + (size_t)(2 * kb)     * 128 + 4 * g);
        wr1[r] = *reinterpret_cast<const float4*>(Wv + (size_t)(2 * kb + 1) * 128 + 4 * g);
    }

    if (t < 64) {
        float* r = sw + t * SWS;
        float m = r[0];
#pragma unroll
        for (int n = 1; n < 49; n++) m = fmaxf(m, r[n]);
        float e[49]; float sum = 0.0f;
#pragma unroll
        for (int n = 0; n < 49; n++) { e[n] = __expf(r[n] - m); sum += e[n]; }
        float inv = 1.0f / sum;
#pragma unroll
        for (int n = 0; n < 49; n++) r[n] = e[n] * inv;
    }
    asm volatile("cp.async.wait_group 0;");
    __syncthreads();

    // ---- Phase 4: AV. thread = (p, sub); sub owns chunks {sub, sub+16} ----
    u64 acc4[4];
#pragma unroll
    for (int j = 0; j < 4; j++) acc4[j] = 0ull;
    {
        const float* wr = sw + p * SWS;
        int n = 0;
        for (int dy = 0; dy < 7; dy++) {
            const float* base0 = sv + ((pry + dy) * WIN + prx) * SVS + sub * 4;
#pragma unroll
            for (int dx = 0; dx < 7; dx++) {
                u64 w2 = dup2(wr[n]);
                const float* vr = base0 + dx * SVS;
                u64 va, vb, vc, vd;
                lds2(va, vb, vr);          // chunk sub
                lds2(vc, vd, vr + 64);     // chunk sub+16
                fma2(acc4[0], w2, va);
                fma2(acc4[1], w2, vb);
                fma2(acc4[2], w2, vc);
                fma2(acc4[3], w2, vd);
                n++;
            }
        }
    }
    __syncthreads();   // sv/sw/sk lifetimes end

    // ---- Phase 5: store Wv twin tables + attention output ----
#pragma unroll
    for (int r = 0; r < 2; r++) {
        int i = t + 1024 * r;
        int kb = i >> 5, g = i & 31;
        sts2(tabA + kb * 64 + 2 * g, pack2(wr0[r].x, wr1[r].x), pack2(wr0[r].y, wr1[r].y));
        sts2(tabB + kb * 64 + 2 * g, pack2(wr0[r].z, wr1[r].z), pack2(wr0[r].w, wr1[r].w));
    }
    sts2(at + p * ATS + sub * 4,      acc4[0], acc4[1]);
    sts2(at + p * ATS + sub * 4 + 64, acc4[2], acc4[3]);
    __syncthreads();

    // ---- Phase 6: out = relu(at @ Wv + bv). thread = (2 px, 4 cols) ----
    {
        const int p0 = (t >> 5) * 2;        // warp-uniform
        const int g  = t & 31;
        const int c0 = g * 4;

        u64 acc[2][4];
#pragma unroll
        for (int i = 0; i < 2; i++)
#pragma unroll
            for (int j = 0; j < 4; j++) acc[i][j] = 0ull;

#pragma unroll 4
        for (int kb = 0; kb < 64; kb++) {
            u64 a2[2];
            a2[0] = lds1(at + p0 * ATS + kb * 2);           // broadcast
            a2[1] = lds1(at + (p0 + 1) * ATS + kb * 2);
            u64 w0, w1, w2, w3;
            lds2(w0, w1, tabA + kb * 64 + 2 * g);           // 16B lane stride
            lds2(w2, w3, tabB + kb * 64 + 2 * g);
#pragma unroll
            for (int i = 0; i < 2; i++) {
                fma2(acc[i][0], a2[i], w0);
                fma2(acc[i][1], a2[i], w1);
                fma2(acc[i][2], a2[i], w2);
                fma2(acc[i][3], a2[i], w3);
            }
        }

        float b0 = bv[c0], b1 = bv[c0 + 1], b2 = bv[c0 + 2], b3 = bv[c0 + 3];
#pragma unroll
        for (int i = 0; i < 2; i++) {
            int pp = p0 + i;
            int py = ty0 + (pp >> 3), px = tx0 + (pp & 7);
            float4 o;
            o.x = fmaxf(hsum2(acc[i][0]) + b0, 0.0f);
            o.y = fmaxf(hsum2(acc[i][1]) + b1, 0.0f);
            o.z = fmaxf(hsum2(acc[i][2]) + b2, 0.0f);
            o.w = fmaxf(hsum2(acc[i][3]) + b3, 0.0f);
            *reinterpret_cast<float4*>(
                out + ((size_t)(b * HH + py) * WW + px) * CC + c0) = o;
        }
    }
}

// ---------------------------------------------------------------------------
extern "C" void kernel_launch(void* const* d_in, const int* in_sizes, int n_in,
                              void* d_out, int out_size)
{
    const float* Q  = (const float*)d_in[0];
    const float* K  = (const float*)d_in[1];
    const float* V  = (const float*)d_in[2];
    const float* Wq = (const float*)d_in[3];
    const float* bq = (const float*)d_in[4];
    const float* Wk = (const float*)d_in[5];
    const float* bk = (const float*)d_in[6];
    const float* Wv = (const float*)d_in[7];
    const float* bv = (const float*)d_in[8];
    float* out = (float*)d_out;

    float *qp, *kp;
    cudaGetSymbolAddress((void**)&qp, g_q);
    cudaGetSymbolAddress((void**)&kp, g_k);

    const int smem_qk   = 128 * ASP * 4 + 2 * 64 * 32 * 8;  // 100,352 B
    const int smem_attn = SM_FLOATS * 4;                    // 170,112 B

    cudaFuncSetAttribute((const void*)gemm_qk_kernel,
                         cudaFuncAttributeMaxDynamicSharedMemorySize, smem_qk);
    cudaFuncSetAttribute((const void*)attn_fused_kernel,
                         cudaFuncAttributeMaxDynamicSharedMemorySize, smem_attn);

    // q/k projections: 288 CTAs, 2/SM, single wave, 32 warps/SM
    gemm_qk_kernel<<<dim3(NPIX / 128, 2), 512, smem_qk>>>(Q, K, Wq, Wk, bq, bk, qp, kp);

    // fused attention + output projection: 288 CTAs, 1024 threads
    dim3 agrid(WW / TS, HH / TS, BATCH);  // (12,12,2)
    attn_fused_kernel<<<agrid, 1024, smem_attn>>>(qp, kp, V, Wv, bv, out);
}

// round 12
// speedup vs baseline: 1.1942x; 1.1942x over previous
#include <cuda_runtime.h>
#include <cstdint>

typedef unsigned long long u64;

#define BATCH 2
#define HH 96
#define WW 96
#define CC 128
#define KD 64
#define NPIX (BATCH * HH * WW)   // 18432

__device__ float g_q[NPIX * KD];
__device__ float g_k[NPIX * KD];

// ---- packed f32x2 helpers ----
__device__ __forceinline__ u64 pack2(float lo, float hi) {
    u64 r; asm("mov.b64 %0, {%1, %2};" : "=l"(r) : "f"(lo), "f"(hi)); return r;
}
__device__ __forceinline__ u64 dup2(float v) { return pack2(v, v); }
__device__ __forceinline__ void fma2(u64& d, u64 a, u64 b) {
    asm("fma.rn.f32x2 %0, %1, %2, %0;" : "+l"(d) : "l"(a), "l"(b));
}
__device__ __forceinline__ float hsum2(u64 v) {
    float lo, hi; asm("mov.b64 {%0, %1}, %2;" : "=f"(lo), "=f"(hi) : "l"(v));
    return lo + hi;
}
__device__ __forceinline__ void lds2(u64& a, u64& b, const void* p) {  // 16B aligned
    unsigned ad = (unsigned)__cvta_generic_to_shared(p);
    asm("ld.shared.v2.b64 {%0, %1}, [%2];" : "=l"(a), "=l"(b) : "r"(ad));
}
__device__ __forceinline__ u64 lds1(const void* p) {                   // 8B aligned
    unsigned ad = (unsigned)__cvta_generic_to_shared(p);
    u64 r; asm("ld.shared.b64 %0, [%1];" : "=l"(r) : "r"(ad)); return r;
}
__device__ __forceinline__ void sts2(void* p, u64 a, u64 b) {
    unsigned ad = (unsigned)__cvta_generic_to_shared(p);
    asm volatile("st.shared.v2.b64 [%0], {%1, %2};" :: "r"(ad), "l"(a), "l"(b));
}
__device__ __forceinline__ void cpasync16(float* dst, const float* src, int sz) {
    unsigned daddr = (unsigned)__cvta_generic_to_shared(dst);
    asm volatile("cp.async.cg.shared.global [%0], [%1], 16, %2;"
                 :: "r"(daddr), "l"(src), "r"(sz));
}

// ---------------------------------------------------------------------------
// q/k projection (round-8 champion version, unchanged).
// ---------------------------------------------------------------------------
#define ASP 132

__global__ __launch_bounds__(256, 2) void gemm_qk_kernel(
    const float* __restrict__ Q,  const float* __restrict__ K,
    const float* __restrict__ Wq, const float* __restrict__ Wk,
    const float* __restrict__ bq, const float* __restrict__ bk,
    float* __restrict__ qout,     float* __restrict__ kout)
{
    extern __shared__ float smf[];
    float* As   = smf;                         // [128][132]
    u64*   tabA = (u64*)(smf + 128 * ASP);     // [64 kb][32]
    u64*   tabB = tabA + 64 * 32;              // [64 kb][32]

    const bool isK = (blockIdx.y != 0);
    const float* A    = isK ? K    : Q;
    const float* W    = isK ? Wk   : Wq;
    const float* bias = isK ? bk   : bq;
    float*       C    = isK ? kout : qout;

    const int m0 = blockIdx.x * 128;
    const int t  = threadIdx.x;

    for (int i = t; i < 4096; i += 256) {
        int r = i >> 5, c4 = i & 31;
        float4 v = *reinterpret_cast<const float4*>(A + (size_t)(m0 + r) * 128 + c4 * 4);
        *reinterpret_cast<float4*>(As + r * ASP + c4 * 4) = v;
    }
    for (int i = t; i < 1024; i += 256) {
        int kb = i >> 4, g = i & 15;
        float4 r0 = *reinterpret_cast<const float4*>(W + (size_t)(2 * kb)     * 64 + 4 * g);
        float4 r1 = *reinterpret_cast<const float4*>(W + (size_t)(2 * kb + 1) * 64 + 4 * g);
        sts2(tabA + kb * 32 + 2 * g, pack2(r0.x, r1.x), pack2(r0.y, r1.y));
        sts2(tabB + kb * 32 + 2 * g, pack2(r0.z, r1.z), pack2(r0.w, r1.w));
    }
    __syncthreads();

    const int ty = t >> 4, tx = t & 15;
    const int col0 = tx * 4;

    u64 acc[8][4];
#pragma unroll
    for (int i = 0; i < 8; i++)
#pragma unroll
        for (int j = 0; j < 4; j++) acc[i][j] = 0ull;

#pragma unroll 4
    for (int kb = 0; kb < 64; kb++) {
        u64 a2[8];
#pragma unroll
        for (int i = 0; i < 8; i++)
            a2[i] = lds1(As + (ty + 16 * i) * ASP + kb * 2);
        u64 w0, w1, w2, w3;
        lds2(w0, w1, tabA + kb * 32 + 2 * tx);
        lds2(w2, w3, tabB + kb * 32 + 2 * tx);
#pragma unroll
        for (int i = 0; i < 8; i++) {
            fma2(acc[i][0], a2[i], w0);
            fma2(acc[i][1], a2[i], w1);
            fma2(acc[i][2], a2[i], w2);
            fma2(acc[i][3], a2[i], w3);
        }
    }

    float b0 = bias[col0], b1 = bias[col0 + 1], b2 = bias[col0 + 2], b3 = bias[col0 + 3];
#pragma unroll
    for (int i = 0; i < 8; i++) {
        int row = m0 + ty + 16 * i;
        float4 o;
        o.x = hsum2(acc[i][0]) + b0;
        o.y = hsum2(acc[i][1]) + b1;
        o.z = hsum2(acc[i][2]) + b2;
        o.w = hsum2(acc[i][3]) + b3;
        *reinterpret_cast<float4*>(C + (size_t)row * 64 + col0) = o;
    }
}

// ---------------------------------------------------------------------------
// Fused attention + output projection. 8x8 pixel tile, 512 threads, 288 CTAs.
// smem (floats): sk[196][68] | sw[64][52] | wt[98][64] | sv[196][132]
// Overlays: twin Wv pair-tables (64KB) over sk+sw (after ph4);
//           at[64][132] over sv.
// ---------------------------------------------------------------------------
#define TS 8
#define WIN 14
#define SKS 68
#define SVS 132
#define SWS 52
#define ATS 132
#define OFF_SK 0
#define OFF_SW (196 * SKS)               // 13328
#define OFF_WT (OFF_SW + 64 * SWS)       // 16656
#define OFF_SV (OFF_WT + 98 * 64)        // 22928
#define SM_FLOATS (OFF_SV + 196 * SVS)   // 48800 -> 195,200 B

__global__ __launch_bounds__(512, 1) void attn_fused_kernel(
    const float* __restrict__ qbuf,
    const float* __restrict__ kbuf,
    const float* __restrict__ V,
    const float* __restrict__ Wv,
    const float* __restrict__ bv,
    float* __restrict__ out)
{
    extern __shared__ float sm[];
    float* sk   = sm + OFF_SK;       // [196][68]
    float* sw   = sm + OFF_SW;       // [64][52]  raw scores
    float* wt   = sm + OFF_WT;       // [98][64]  zero-padded transposed weights
    float* sv   = sm + OFF_SV;       // [196][132]
    u64*   tabA = (u64*)sm;          // overlay: [64 kb][64]  (32KB, over sk)
    u64*   tabB = tabA + 64 * 64;    // overlay: [64 kb][64]  (ends at 64KB < OFF_WT*4)
    float* at   = sv;                // overlay: [64][132]

    const int b   = blockIdx.z;
    const int ty0 = blockIdx.y * TS;
    const int tx0 = blockIdx.x * TS;
    const int t   = threadIdx.x;

    const int p   = t >> 3;                 // pixel 0..63
    const int sub = t & 7;                  // 0..7
    const int pry = p >> 3, prx = p & 7;

    // ---- Phase 1: cp.async V halo -> sv; LDG k halo -> sk; zero wt ----
    for (int i = t; i < 196 * 32; i += 512) {
        int r = i >> 5, c4 = i & 31;
        int gy = ty0 - 3 + r / WIN;
        int gx = tx0 - 3 + r % WIN;
        bool ok = (gy >= 0 && gy < HH && gx >= 0 && gx < WW);
        const float* src = V + ((size_t)(b * HH + (ok ? gy : 0)) * WW + (ok ? gx : 0)) * CC + c4 * 4;
        cpasync16(sv + r * SVS + c4 * 4, src, ok ? 16 : 0);
    }
    asm volatile("cp.async.commit_group;");

    for (int i = t; i < 98 * 64; i += 512) wt[i] = 0.0f;

    for (int i = t; i < 196 * 16; i += 512) {
        int r = i >> 4, c4 = i & 15;
        int gy = ty0 - 3 + r / WIN;
        int gx = tx0 - 3 + r % WIN;
        float4 v = make_float4(0.f, 0.f, 0.f, 0.f);
        if (gy >= 0 && gy < HH && gx >= 0 && gx < WW)
            v = *reinterpret_cast<const float4*>(
                kbuf + ((size_t)(b * HH + gy) * WW + gx) * KD + c4 * 4);
        *reinterpret_cast<float4*>(sk + r * SKS + c4 * 4) = v;
    }
    __syncthreads();

    // ---- Phase 2: scores (round-8 exact: full 64 channels, uniform iters) ----
    {
        const int chh = sub >> 2;
        const int ng  = sub & 3;

        u64 q2[16];
        {
            const float* qp_ = qbuf + ((size_t)(b * HH + ty0 + pry) * WW + tx0 + prx) * KD;
#pragma unroll
            for (int j = 0; j < 8; j++) {
                ulonglong2 v = *reinterpret_cast<const ulonglong2*>(qp_ + j * 8 + chh * 4);
                q2[2 * j] = v.x; q2[2 * j + 1] = v.y;
            }
        }

#pragma unroll 2
        for (int ni = 0; ni < 13; ni++) {
            const int n  = ng + ni * 4;
            const int nc = (n < 49) ? n : 48;          // clamp: safe compute
            const int dy = nc / 7, dx = nc - dy * 7;
            const float* kr = sk + ((pry + dy) * WIN + prx + dx) * SKS + chh * 4;
            u64 a0 = 0ull, a1 = 0ull;
#pragma unroll
            for (int j = 0; j < 8; j++) {
                u64 ka, kb2;
                lds2(ka, kb2, kr + j * 8);             // 16B lane stride across chh
                fma2(a0, q2[2 * j], ka);
                fma2(a1, q2[2 * j + 1], kb2);
            }
            float part = hsum2(a0) + hsum2(a1);
            part += __shfl_xor_sync(0xffffffffu, part, 4);   // combine chh halves
            if (chh == 0 && n < 49) {
                int gy = ty0 + pry + dy - 3, gx = tx0 + prx + dx - 3;
                bool valid = (gy >= 0 && gy < HH && gx >= 0 && gx < WW);
                sw[p * SWS + n] = valid ? part * 0.125f : -1e30f;
            }
        }
    }
    __syncthreads();

    // ---- Phase 3: prefetch Wv rows into regs (round-8); softmax -> wt ----
    float4 wr0[4], wr1[4];
#pragma unroll
    for (int r = 0; r < 4; r++) {
        int i = t + 512 * r;                 // (kb 0..63) x (g 0..31)
        int kb = i >> 5, g = i & 31;
        wr0[r] = *reinterpret_cast<const float4*>(Wv + (size_t)(2 * kb)     * 128 + 4 * g);
        wr1[r] = *reinterpret_cast<const float4*>(Wv + (size_t)(2 * kb + 1) * 128 + 4 * g);
    }

    if (t < 64) {
        const int ppx = t & 7;
        float* r = sw + t * SWS;
        float m = r[0];
#pragma unroll
        for (int n = 1; n < 49; n++) m = fmaxf(m, r[n]);
        float e[49]; float sum = 0.0f;
#pragma unroll
        for (int n = 0; n < 49; n++) { e[n] = __expf(r[n] - m); sum += e[n]; }
        float inv = 1.0f / sum;
#pragma unroll
        for (int n = 0; n < 49; n++) {
            int dy = n / 7, dx = n - dy * 7;
            wt[(dy * 14 + ppx + dx) * 64 + t] = e[n] * inv;
        }
    }
    asm volatile("cp.async.wait_group 0;");
    __syncthreads();

    // ---- Phase 4: AV row-sharing. warp = (row, half); lanes = dense channels ----
    // thread: 4 pixels (row4*8 + half4*4 + i) x 4 channels (cc4*4..+3).
    const int row4  = t >> 6;          // 0..7
    const int half4 = (t >> 5) & 1;    // 0/1
    const int cc4   = t & 31;          // 0..31

    u64 acc4[4][2];
#pragma unroll
    for (int i = 0; i < 4; i++) { acc4[i][0] = 0ull; acc4[i][1] = 0ull; }

    for (int dy = 0; dy < 7; dy++) {
        const float* svrow = sv + ((row4 + dy) * WIN + half4 * 4) * SVS + cc4 * 4;
        const float* wrow  = wt + (dy * 14 + half4 * 4) * 64 + row4 * 8 + half4 * 4;
#pragma unroll
        for (int wxi = 0; wxi < 10; wxi++) {
            u64 va, vb;
            lds2(va, vb, svrow + wxi * SVS);                 // dense 16B/lane, conflict-free
            float4 w4 = *reinterpret_cast<const float4*>(wrow + wxi * 64);   // broadcast
            u64 w0 = dup2(w4.x), w1 = dup2(w4.y), w2 = dup2(w4.z), w3 = dup2(w4.w);
            fma2(acc4[0][0], w0, va); fma2(acc4[0][1], w0, vb);
            fma2(acc4[1][0], w1, va); fma2(acc4[1][1], w1, vb);
            fma2(acc4[2][0], w2, va); fma2(acc4[2][1], w2, vb);
            fma2(acc4[3][0], w3, va); fma2(acc4[3][1], w3, vb);
        }
    }
    __syncthreads();   // sv/sk/sw/wt reads done

    // ---- Phase 5: store Wv twin tables (round-8 exact) + at ----
#pragma unroll
    for (int r = 0; r < 4; r++) {
        int i = t + 512 * r;
        int kb = i >> 5, g = i & 31;
        sts2(tabA + kb * 64 + 2 * g, pack2(wr0[r].x, wr1[r].x), pack2(wr0[r].y, wr1[r].y));
        sts2(tabB + kb * 64 + 2 * g, pack2(wr0[r].z, wr1[r].z), pack2(wr0[r].w, wr1[r].w));
    }
#pragma unroll
    for (int i = 0; i < 4; i++) {
        int px = row4 * 8 + half4 * 4 + i;
        sts2(at + px * ATS + cc4 * 4, acc4[i][0], acc4[i][1]);
    }
    __syncthreads();

    // ---- Phase 6: out = relu(at @ Wv + bv) (round-8 exact: 4 px x 4 cols) ----
    {
        const int p0 = (t >> 5) * 4;        // warp-uniform -> broadcast a-loads
        const int g  = t & 31;
        const int c0 = g * 4;

        u64 acc[4][4];
#pragma unroll
        for (int i = 0; i < 4; i++)
#pragma unroll
            for (int j = 0; j < 4; j++) acc[i][j] = 0ull;

#pragma unroll 4
        for (int kb = 0; kb < 64; kb++) {
            u64 a2[4];
#pragma unroll
            for (int i = 0; i < 4; i++)
                a2[i] = lds1(at + (p0 + i) * ATS + kb * 2);    // uniform addr: broadcast
            u64 w0, w1, w2, w3;
            lds2(w0, w1, tabA + kb * 64 + 2 * g);              // 16B lane stride
            lds2(w2, w3, tabB + kb * 64 + 2 * g);
#pragma unroll
            for (int i = 0; i < 4; i++) {
                fma2(acc[i][0], a2[i], w0);
                fma2(acc[i][1], a2[i], w1);
                fma2(acc[i][2], a2[i], w2);
                fma2(acc[i][3], a2[i], w3);
            }
        }

        float b0 = bv[c0], b1 = bv[c0 + 1], b2 = bv[c0 + 2], b3 = bv[c0 + 3];
#pragma unroll
        for (int i = 0; i < 4; i++) {
            int pp = p0 + i;
            int py = ty0 + (pp >> 3), px = tx0 + (pp & 7);
            float4 o;
            o.x = fmaxf(hsum2(acc[i][0]) + b0, 0.0f);
            o.y = fmaxf(hsum2(acc[i][1]) + b1, 0.0f);
            o.z = fmaxf(hsum2(acc[i][2]) + b2, 0.0f);
            o.w = fmaxf(hsum2(acc[i][3]) + b3, 0.0f);
            *reinterpret_cast<float4*>(
                out + ((size_t)(b * HH + py) * WW + px) * CC + c0) = o;
        }
    }
}

// ---------------------------------------------------------------------------
extern "C" void kernel_launch(void* const* d_in, const int* in_sizes, int n_in,
                              void* d_out, int out_size)
{
    const float* Q  = (const float*)d_in[0];
    const float* K  = (const float*)d_in[1];
    const float* V  = (const float*)d_in[2];
    const float* Wq = (const float*)d_in[3];
    const float* bq = (const float*)d_in[4];
    const float* Wk = (const float*)d_in[5];
    const float* bk = (const float*)d_in[6];
    const float* Wv = (const float*)d_in[7];
    const float* bv = (const float*)d_in[8];
    float* out = (float*)d_out;

    float *qp, *kp;
    cudaGetSymbolAddress((void**)&qp, g_q);
    cudaGetSymbolAddress((void**)&kp, g_k);

    const int smem_qk   = 128 * ASP * 4 + 2 * 64 * 32 * 8;  // 100,352 B
    const int smem_attn = SM_FLOATS * 4;                    // 195,200 B

    cudaFuncSetAttribute((const void*)gemm_qk_kernel,
                         cudaFuncAttributeMaxDynamicSharedMemorySize, smem_qk);
    cudaFuncSetAttribute((const void*)attn_fused_kernel,
                         cudaFuncAttributeMaxDynamicSharedMemorySize, smem_attn);

    // q/k projections: 288 CTAs, 2/SM, single wave
    gemm_qk_kernel<<<dim3(NPIX / 128, 2), 256, smem_qk>>>(Q, K, Wq, Wk, bq, bk, qp, kp);

    // fused attention + output projection: 288 CTAs
    dim3 agrid(WW / TS, HH / TS, BATCH);  // (12,12,2)
    attn_fused_kernel<<<agrid, 512, smem_attn>>>(qp, kp, V, Wv, bv, out);
}